// round 17
// baseline (speedup 1.0000x reference)
#include <cuda_runtime.h>
#include <cuda_fp16.h>
#include <cstdint>

// TransitionLayer: BN(eval)+ReLU+1x1conv(512->256)+avgpool2x2, NCHW fp32.
// pool(conv(act)) == conv(pool(act)) -> GEMM M=50176, K=512, N=256.
// R17: PERSISTENT warp-specialized kernel. grid=148; each CTA loops tiles
//      bid+148t. Producer/consumer ring indexed by a global chunk counter g
//      (8 stages, named barriers full=0..7 / empty=8..15) that runs across
//      tile boundaries -> pipeline fill/drain paid once per CTA, not per tile.
//      Inner bodies = R16 (64m x 32n consumers, B reg pipeline, 1-term fp16).

#define BN_EPS 1e-5f

constexpr int CIN  = 512;
constexpr int HH   = 56;
constexpr int WW   = 56;
constexpr int HW   = HH * WW;           // 3136
constexpr int COUT = 256;
constexpr int PP   = 28;
constexpr int PIX  = PP * PP;           // 784
constexpr int M_TOTAL = 64 * PIX;       // 50176
constexpr int MT   = 64;
constexpr int NT   = M_TOTAL / MT;      // 784 tiles
constexpr int BK   = 32;
constexpr int NCH  = CIN / BK;          // 16 chunks per tile
constexpr int NSTG = 8;                 // ring stages
constexpr int GRID = 148;

// A fp16 tile: row = 64B data + 16B pad = 80B stride (conflict-free ldmatrix).
constexpr int ARSB    = 80;
constexpr int A_BYTES = MT * ARSB;      // 5120 per stage
constexpr int TILE_OFF = 4096;
constexpr int SM_TOTAL = TILE_OFF + NSTG * A_BYTES;   // 45056

// Prepacked B frags (fp16): [kc 32][nb 32][lane 32] -> uint2 {b0,b1}
constexpr int BUNITS = 32 * 32 * 32;
__device__ __align__(16) uint2 g_Bfrag[BUNITS];

#define MMA_F16(C, A, B0, B1)                                                \
    asm volatile("mma.sync.aligned.m16n8k16.row.col.f32.f16.f16.f32 "        \
                 "{%0,%1,%2,%3}, {%4,%5,%6,%7}, {%8,%9}, {%0,%1,%2,%3};"     \
                 : "+f"((C)[0]), "+f"((C)[1]), "+f"((C)[2]), "+f"((C)[3])    \
                 : "r"((A)[0]), "r"((A)[1]), "r"((A)[2]), "r"((A)[3]),       \
                   "r"(B0), "r"(B1))

#define LDMX4(R, ADDR)                                                       \
    asm volatile("ldmatrix.sync.aligned.m8n8.x4.shared.b16 {%0,%1,%2,%3}, [%4];" \
                 : "=r"((R)[0]), "=r"((R)[1]), "=r"((R)[2]), "=r"((R)[3])    \
                 : "r"(ADDR))

#define BAR_SYNC(id)   asm volatile("bar.sync %0, 512;"   :: "r"(id) : "memory")
#define BAR_ARRIVE(id) asm volatile("bar.arrive %0, 512;" :: "r"(id) : "memory")

__device__ __forceinline__ uint32_t smem_u32(const void* p) {
    uint32_t a;
    asm("{ .reg .u64 t; cvta.to.shared.u64 t, %1; cvt.u32.u64 %0, t; }" : "=r"(a) : "l"(p));
    return a;
}
__device__ __forceinline__ uint32_t pack2_f16(float v0, float v1) {
    __half h0 = __float2half_rn(v0);
    __half h1 = __float2half_rn(v1);
    return (uint32_t)__half_as_ushort(h0) | ((uint32_t)__half_as_ushort(h1) << 16);
}
__device__ __forceinline__ void sts64(uint32_t addr, uint32_t a, uint32_t b) {
    asm volatile("st.shared.v2.b32 [%0], {%1,%2};" :: "r"(addr), "r"(a), "r"(b) : "memory");
}

// ---------------- kernel 1: prepack B (fp16, fragment-major) ----------------
__global__ void prepack_B(const float* __restrict__ conv_w)
{
    const int idx = blockIdx.x * 256 + threadIdx.x;
    if (idx >= BUNITS) return;
    const int lane = idx & 31;
    const int nb   = (idx >> 5) & 31;
    const int kc   = idx >> 10;
    const int n  = nb * 8 + (lane >> 2);
    const int k0 = kc * 16 + (lane & 3) * 2;
    const float* wr = conv_w + (size_t)n * CIN;
    g_Bfrag[idx] = make_uint2(pack2_f16(wr[k0],     wr[k0 + 1]),
                              pack2_f16(wr[k0 + 8], wr[k0 + 9]));
}

// ---------------- kernel 2: main (persistent, warp-specialized) ----------------
__global__ __launch_bounds__(512, 1)
void transition_pws_kernel(const float* __restrict__ x,
                           const float* __restrict__ bn_w,
                           const float* __restrict__ bn_b,
                           const float* __restrict__ bn_m,
                           const float* __restrict__ bn_v,
                           float* __restrict__ out)
{
    extern __shared__ __align__(16) uint32_t sm[];
    float* s_scale = reinterpret_cast<float*>(sm);
    float* s_shift = reinterpret_cast<float*>(sm) + 512;
    const uint32_t sbase = smem_u32(sm);
    const uint32_t tile0 = sbase + TILE_OFF;

    const int tid  = threadIdx.x;
    const int wid  = tid >> 5;
    const int lane = tid & 31;
    const int bid  = blockIdx.x;

    const int ntiles = (NT - 1 - bid) / GRID + 1;   // 6 for bid<44, else 5
    const int G = ntiles * NCH;                      // total chunks this CTA

    {   // BN tables: 512 threads, one channel each
        const int c = tid;
        float inv = rsqrtf(bn_v[c] + BN_EPS);
        float sc  = bn_w[c] * inv;
        s_scale[c] = sc;
        s_shift[c] = bn_b[c] - bn_m[c] * sc;
    }
    __syncthreads();

    if (wid >= 8) {
        // ================= PRODUCER (warps 8..15) =================
        const int ptid = tid - 256;
        const int pxl  = ptid >> 2;        // pooled pixel 0..63
        const int aq   = ptid & 3;         // channels aq*8 .. +8

        float2 a0[8], a1[8], b0[8], b1[8];

        auto ldg = [&](int g, float2* r0, float2* r1) {
            const int t   = g >> 4;
            const int mg  = (bid + GRID * t) * MT + pxl;
            const int img = mg / PIX;
            const int pr  = mg % PIX;
            const float* xb = x + (size_t)img * (CIN * HW)
                                + (size_t)(2 * (pr / PP)) * WW + 2 * (pr % PP);
            const int c0 = (g & 15) * BK + aq * 8;
            #pragma unroll
            for (int e = 0; e < 8; e++) {
                const float* xp = xb + (size_t)(c0 + e) * HW;
                r0[e] = *reinterpret_cast<const float2*>(xp);
                r1[e] = *reinterpret_cast<const float2*>(xp + WW);
            }
        };
        auto cvtsts = [&](int g, float2* r0, float2* r1) {
            const int c0 = (g & 15) * BK + aq * 8;
            float v[8];
            #pragma unroll
            for (int e = 0; e < 8; e++) {
                const float sc = s_scale[c0 + e], sh = s_shift[c0 + e];
                v[e] = 0.25f * (fmaxf(fmaf(r0[e].x, sc, sh), 0.0f)
                              + fmaxf(fmaf(r0[e].y, sc, sh), 0.0f)
                              + fmaxf(fmaf(r1[e].x, sc, sh), 0.0f)
                              + fmaxf(fmaf(r1[e].y, sc, sh), 0.0f));
            }
            const uint32_t st = tile0 + (uint32_t)((g & (NSTG - 1)) * A_BYTES)
                              + (uint32_t)(pxl * ARSB + aq * 16);
            sts64(st,     pack2_f16(v[0], v[1]), pack2_f16(v[2], v[3]));
            sts64(st + 8, pack2_f16(v[4], v[5]), pack2_f16(v[6], v[7]));
        };

        ldg(0, a0, a1);
        #pragma unroll 1
        for (int g = 0; g < G; g++) {
            float2* c0r = (g & 1) ? b0 : a0;
            float2* c1r = (g & 1) ? b1 : a1;
            float2* n0r = (g & 1) ? a0 : b0;
            float2* n1r = (g & 1) ? a1 : b1;
            if (g + 1 < G) ldg(g + 1, n0r, n1r);      // next chunk in flight
            if (g >= NSTG) BAR_SYNC(8 + (g & (NSTG - 1)));   // empty(g)
            cvtsts(g, c0r, c1r);
            BAR_ARRIVE(g & (NSTG - 1));                       // full(g)
        }
    } else {
        // ================= CONSUMER (warps 0..7) =================
        float acc[4][4][4];
        #pragma unroll
        for (int mh = 0; mh < 4; mh++)
            #pragma unroll
            for (int nn = 0; nn < 4; nn++)
                #pragma unroll
                for (int e = 0; e < 4; e++) acc[mh][nn][e] = 0.0f;

        const uint32_t a_ldm = (uint32_t)((lane & 15) * ARSB + ((lane >> 4) << 4));
        const uint2* bbase = g_Bfrag + (size_t)(wid * 4) * 32 + lane;

        auto ldB = [&](int kc, uint2* dst) {
            const uint2* bp = bbase + (size_t)kc * (32 * 32);
            #pragma unroll
            for (int nn = 0; nn < 4; nn++) dst[nn] = __ldg(bp + nn * 32);
        };
        auto compute_ks = [&](int g, int ks, const uint2* bcur, uint2* bnxt, int kc_next) {
            const uint32_t aa = tile0 + (uint32_t)((g & (NSTG - 1)) * A_BYTES)
                              + a_ldm + (uint32_t)(ks * 32);
            uint32_t ah[4][4];
            #pragma unroll
            for (int mh = 0; mh < 4; mh++)
                LDMX4(ah[mh], aa + (uint32_t)(mh * 16 * ARSB));
            ldB(kc_next, bnxt);
            #pragma unroll
            for (int nn = 0; nn < 4; nn++) {
                #pragma unroll
                for (int mh = 0; mh < 4; mh++)
                    MMA_F16(acc[mh][nn], ah[mh], bcur[nn].x, bcur[nn].y);
            }
        };

        uint2 bbuf0[4], bbuf1[4];
        ldB(0, bbuf0);

        const int fr = lane >> 2;
        const int q2 = (lane & 3) * 2;

        #pragma unroll 1
        for (int g = 0; g < G; g++) {
            BAR_SYNC(g & (NSTG - 1));                 // wait full(g)
            const int kc1 = (g & 15) * 2 + 1;
            const int kc2 = (g + 1 < G) ? (((g + 1) & 15) * 2) : 0;
            compute_ks(g, 0, bbuf0, bbuf1, kc1);
            compute_ks(g, 1, bbuf1, bbuf0, kc2);
            if (g + NSTG < G)
                BAR_ARRIVE(8 + (g & (NSTG - 1)));     // empty(g)

            if ((g & 15) == 15) {
                // ---------- epilogue for tile t = g>>4 ----------
                const int m0 = (bid + GRID * (g >> 4)) * MT;
                #pragma unroll
                for (int mh = 0; mh < 4; mh++) {
                    #pragma unroll
                    for (int half = 0; half < 2; half++) {
                        const int m  = m0 + mh * 16 + fr + half * 8;
                        const int im = m / PIX;
                        const int px = m % PIX;
                        float* ob = out + (size_t)im * (COUT * PIX) + px;
                        #pragma unroll
                        for (int nn = 0; nn < 4; nn++) {
                            const int n = wid * 32 + nn * 8 + q2;
                            ob[(size_t)n * PIX]       = acc[mh][nn][half * 2];
                            ob[(size_t)(n + 1) * PIX] = acc[mh][nn][half * 2 + 1];
                        }
                    }
                }
                #pragma unroll
                for (int mh = 0; mh < 4; mh++)
                    #pragma unroll
                    for (int nn = 0; nn < 4; nn++)
                        #pragma unroll
                        for (int e = 0; e < 4; e++) acc[mh][nn][e] = 0.0f;
            }
        }
    }
}

extern "C" void kernel_launch(void* const* d_in, const int* in_sizes, int n_in,
                              void* d_out, int out_size)
{
    const float* x      = (const float*)d_in[0];
    const float* bn_w   = (const float*)d_in[1];
    const float* bn_b   = (const float*)d_in[2];
    const float* bn_m   = (const float*)d_in[3];
    const float* bn_v   = (const float*)d_in[4];
    const float* conv_w = (const float*)d_in[5];
    float* out = (float*)d_out;

    prepack_B<<<(BUNITS + 255) / 256, 256>>>(conv_w);

    cudaFuncSetAttribute(transition_pws_kernel,
                         cudaFuncAttributeMaxDynamicSharedMemorySize, SM_TOTAL);
    transition_pws_kernel<<<GRID, 512, SM_TOTAL>>>(
        x, bn_w, bn_b, bn_m, bn_v, out);
}